// round 9
// baseline (speedup 1.0000x reference)
#include <cuda_runtime.h>

#define N_NODES 40000
#define N_EDGES 640000
#define DIN 128
#define DH 128
#define DOUT 64

#define SCAN_B 256
#define SCAN_NB ((N_NODES + SCAN_B - 1) / SCAN_B)   // 157

// ---------------- scratch (no allocations allowed) ----------------
__device__ int   g_is64;                 // 1 if edge_index is int64, 0 if int32
__device__ int   g_cnt[N_NODES];
__device__ int   g_rowptr[N_NODES + 1];
__device__ int   g_cursor[N_NODES];
__device__ int   g_bsum[SCAN_B];
__device__ int   g_boff[SCAN_B];
__device__ int2  g_epack[N_EDGES];       // {src, norm-weight as float bits}
__device__ float g_dinv[N_NODES];
__device__ float g_h1[(size_t)N_NODES * DH];     // x @ W1
__device__ float g_agg1[(size_t)N_NODES * DH];   // layer-1 aggregation (pre relu/bias)
__device__ float g_h2[(size_t)N_NODES * DOUT];   // relu(agg1+b1) @ W2

// ---------------- init: zero counts + dtype detection (block 0) ----------------
// int64 indices < 2^31 => every odd int32 word of the first 4096 pairs is 0.
__global__ void k_init(const int* __restrict__ ei) {
    int i = blockIdx.x * blockDim.x + threadIdx.x;
    if (i < N_NODES) g_cnt[i] = 0;
    if (blockIdx.x == 0) {
        __shared__ int any_nz;
        if (threadIdx.x == 0) any_nz = 0;
        __syncthreads();
        int nz = 0;
        for (int j = threadIdx.x; j < 4096; j += blockDim.x)
            if (ei[2 * j + 1] != 0) nz = 1;
        if (nz) any_nz = 1;
        __syncthreads();
        if (threadIdx.x == 0) g_is64 = any_nz ? 0 : 1;
    }
}

__device__ __forceinline__ int edge_idx(const void* ei, int which, int e, int is64) {
    if (is64) return (int)((const long long*)ei)[(size_t)which * N_EDGES + e];
    return ((const int*)ei)[which * N_EDGES + e];
}

// ---------------- CSR build ----------------
__global__ void k_count(const void* __restrict__ ei) {
    int e = blockIdx.x * blockDim.x + threadIdx.x;
    if (e < N_EDGES) {
        int d = edge_idx(ei, 1, e, g_is64);
        if ((unsigned)d < N_NODES) atomicAdd(&g_cnt[d], 1);
    }
}

// ---- 3-phase exclusive scan of g_cnt -> rowptr/cursor (+ dinv) ----
__global__ void k_scan_a() {
    __shared__ int sh[SCAN_B];
    int i = blockIdx.x * SCAN_B + threadIdx.x;
    int v = (i < N_NODES) ? g_cnt[i] : 0;
    sh[threadIdx.x] = v;
    __syncthreads();
#pragma unroll
    for (int off = 1; off < SCAN_B; off <<= 1) {
        int t = (threadIdx.x >= off) ? sh[threadIdx.x - off] : 0;
        __syncthreads();
        sh[threadIdx.x] += t;
        __syncthreads();
    }
    if (i < N_NODES) g_rowptr[i] = sh[threadIdx.x] - v;   // local exclusive
    if (threadIdx.x == SCAN_B - 1) g_bsum[blockIdx.x] = sh[threadIdx.x];
}

__global__ void k_scan_b() {
    __shared__ int sh[SCAN_B];
    int v = (threadIdx.x < SCAN_NB) ? g_bsum[threadIdx.x] : 0;
    sh[threadIdx.x] = v;
    __syncthreads();
#pragma unroll
    for (int off = 1; off < SCAN_B; off <<= 1) {
        int t = (threadIdx.x >= off) ? sh[threadIdx.x - off] : 0;
        __syncthreads();
        sh[threadIdx.x] += t;
        __syncthreads();
    }
    if (threadIdx.x < SCAN_NB) g_boff[threadIdx.x] = sh[threadIdx.x] - v;  // exclusive
    if (threadIdx.x == SCAN_NB - 1) g_rowptr[N_NODES] = sh[threadIdx.x];   // grand total
}

__global__ void k_scan_c() {
    int i = blockIdx.x * SCAN_B + threadIdx.x;
    if (i < N_NODES) {
        int r = g_rowptr[i] + g_boff[blockIdx.x];
        g_rowptr[i] = r;
        g_cursor[i] = r;
        g_dinv[i] = rsqrtf((float)(g_cnt[i] + 1));   // +1 self-loop
    }
}

// fill buckets; precompute per-edge normalization weight, pack {src, w}
__global__ void k_fill(const void* __restrict__ ei) {
    int e = blockIdx.x * blockDim.x + threadIdx.x;
    if (e < N_EDGES) {
        int is64 = g_is64;
        int d = edge_idx(ei, 1, e, is64);
        int s = edge_idx(ei, 0, e, is64);
        if ((unsigned)d < N_NODES && (unsigned)s < N_NODES) {
            int pos = atomicAdd(&g_cursor[d], 1);
            float w = g_dinv[s] * g_dinv[d];
            g_epack[pos] = make_int2(s, __float_as_int(w));
        }
    }
}

// ---------------- tiled fp32 GEMM: C[M,BN] = op(A[M,128]) @ W[128,BN] ----------------
// BM=128, BK=16, 256 threads (16x16), micro-tile TM=8 x TN=BN/16.
template <int BN, bool RELU_BIAS>
__global__ void k_gemm(const float* __restrict__ A, const float* __restrict__ W,
                       const float* __restrict__ bias, float* __restrict__ C) {
    constexpr int K = 128, BM = 128, BK = 16;
    constexpr int TM = 8;
    constexpr int TN = BN / 16;              // 8 (BN=128) or 4 (BN=64)

    __shared__ float As[BK][BM];             // A transposed for LDS.128 fragments
    __shared__ float Ws[BK][BN];
    __shared__ float bsh[K];

    const int tid = threadIdx.x;
    const int block_row = blockIdx.x * BM;
    const int tx = tid & 15;                 // 0..15 (col group)
    const int ty = tid >> 4;                 // 0..15 (row group)

    if (RELU_BIAS) {
        if (tid < K) bsh[tid] = bias[tid];
        __syncthreads();
    }

    float acc[TM][TN];
#pragma unroll
    for (int r = 0; r < TM; r++)
#pragma unroll
        for (int c = 0; c < TN; c++) acc[r][c] = 0.0f;

    for (int k0 = 0; k0 < K; k0 += BK) {
        // load A tile: 128 rows x 16 cols = 512 float4, 2 per thread, store transposed
#pragma unroll
        for (int L = 0; L < 2; L++) {
            int idx = tid + L * 256;         // 0..511
            int row = idx >> 2;              // 0..127
            int kq = (idx & 3) * 4;
            int grow = block_row + row;
            float4 a;
            if (grow < N_NODES) {
                a = *(const float4*)(A + (size_t)grow * K + k0 + kq);
                if (RELU_BIAS) {
                    a.x = fmaxf(a.x + bsh[k0 + kq + 0], 0.0f);
                    a.y = fmaxf(a.y + bsh[k0 + kq + 1], 0.0f);
                    a.z = fmaxf(a.z + bsh[k0 + kq + 2], 0.0f);
                    a.w = fmaxf(a.w + bsh[k0 + kq + 3], 0.0f);
                }
            } else {
                a = make_float4(0.f, 0.f, 0.f, 0.f);
            }
            As[kq + 0][row] = a.x;
            As[kq + 1][row] = a.y;
            As[kq + 2][row] = a.z;
            As[kq + 3][row] = a.w;
        }
        // load W tile: BK x BN
        constexpr int WLOADS = (BK * BN / 4) / 256;   // 2 or 1
#pragma unroll
        for (int L = 0; L < WLOADS; L++) {
            int idx = tid + L * 256;
            int r = idx / (BN / 4);
            int cq = (idx % (BN / 4)) * 4;
            *(float4*)&Ws[r][cq] = *(const float4*)(W + (size_t)(k0 + r) * BN + cq);
        }
        __syncthreads();

#pragma unroll
        for (int kk = 0; kk < BK; kk++) {
            float af[TM], bf[TN];
            *(float4*)&af[0] = *(const float4*)&As[kk][ty * TM];
            *(float4*)&af[4] = *(const float4*)&As[kk][ty * TM + 4];
            *(float4*)&bf[0] = *(const float4*)&Ws[kk][tx * TN];
            if (TN == 8) *(float4*)&bf[4] = *(const float4*)&Ws[kk][tx * TN + 4];
#pragma unroll
            for (int r = 0; r < TM; r++)
#pragma unroll
                for (int c = 0; c < TN; c++)
                    acc[r][c] = fmaf(af[r], bf[c], acc[r][c]);
        }
        __syncthreads();
    }

#pragma unroll
    for (int r = 0; r < TM; r++) {
        int grow = block_row + ty * TM + r;
        if (grow < N_NODES) {
#pragma unroll
            for (int cq = 0; cq < TN; cq += 4) {
                float4 o = make_float4(acc[r][cq], acc[r][cq + 1], acc[r][cq + 2], acc[r][cq + 3]);
                *(float4*)(C + (size_t)grow * BN + tx * TN + cq) = o;
            }
        }
    }
}

// ---------------- gather aggregation, layer 1 (C=128): one warp per node ----------------
__global__ void k_gather1() {
    int node = (blockIdx.x * blockDim.x + threadIdx.x) >> 5;
    if (node >= N_NODES) return;
    int lane = threadIdx.x & 31;

    float dd = g_dinv[node];
    float self = dd * dd;
    float4 acc = ((const float4*)(g_h1 + (size_t)node * DH))[lane];
    acc.x *= self; acc.y *= self; acc.z *= self; acc.w *= self;

    int e = g_rowptr[node];
    int end = g_rowptr[node + 1];
    for (; e + 3 < end; e += 4) {
        int2 p0 = g_epack[e],     p1 = g_epack[e + 1];
        int2 p2 = g_epack[e + 2], p3 = g_epack[e + 3];
        float w0 = __int_as_float(p0.y), w1 = __int_as_float(p1.y);
        float w2 = __int_as_float(p2.y), w3 = __int_as_float(p3.y);
        float4 v0 = ((const float4*)(g_h1 + (size_t)p0.x * DH))[lane];
        float4 v1 = ((const float4*)(g_h1 + (size_t)p1.x * DH))[lane];
        float4 v2 = ((const float4*)(g_h1 + (size_t)p2.x * DH))[lane];
        float4 v3 = ((const float4*)(g_h1 + (size_t)p3.x * DH))[lane];
        acc.x = fmaf(v0.x, w0, fmaf(v1.x, w1, fmaf(v2.x, w2, fmaf(v3.x, w3, acc.x))));
        acc.y = fmaf(v0.y, w0, fmaf(v1.y, w1, fmaf(v2.y, w2, fmaf(v3.y, w3, acc.y))));
        acc.z = fmaf(v0.z, w0, fmaf(v1.z, w1, fmaf(v2.z, w2, fmaf(v3.z, w3, acc.z))));
        acc.w = fmaf(v0.w, w0, fmaf(v1.w, w1, fmaf(v2.w, w2, fmaf(v3.w, w3, acc.w))));
    }
    for (; e < end; e++) {
        int2 p = g_epack[e];
        float w = __int_as_float(p.y);
        float4 v = ((const float4*)(g_h1 + (size_t)p.x * DH))[lane];
        acc.x = fmaf(v.x, w, acc.x);
        acc.y = fmaf(v.y, w, acc.y);
        acc.z = fmaf(v.z, w, acc.z);
        acc.w = fmaf(v.w, w, acc.w);
    }
    ((float4*)(g_agg1 + (size_t)node * DH))[lane] = acc;
}

// ---------------- gather aggregation, layer 2 (C=64): half-warp per node, + b2 ----------------
__global__ void k_gather2(const float* __restrict__ b2, float* __restrict__ out) {
    int gw = (blockIdx.x * blockDim.x + threadIdx.x) >> 5;
    int lane = threadIdx.x & 31;
    int node = gw * 2 + (lane >> 4);
    if (node >= N_NODES) return;
    int l = lane & 15;  // 16 lanes x float4 = 64 floats

    float dd = g_dinv[node];
    float self = dd * dd;
    float4 acc = ((const float4*)(g_h2 + (size_t)node * DOUT))[l];
    acc.x *= self; acc.y *= self; acc.z *= self; acc.w *= self;

    int e = g_rowptr[node];
    int end = g_rowptr[node + 1];
    for (; e + 3 < end; e += 4) {
        int2 p0 = g_epack[e],     p1 = g_epack[e + 1];
        int2 p2 = g_epack[e + 2], p3 = g_epack[e + 3];
        float w0 = __int_as_float(p0.y), w1 = __int_as_float(p1.y);
        float w2 = __int_as_float(p2.y), w3 = __int_as_float(p3.y);
        float4 v0 = ((const float4*)(g_h2 + (size_t)p0.x * DOUT))[l];
        float4 v1 = ((const float4*)(g_h2 + (size_t)p1.x * DOUT))[l];
        float4 v2 = ((const float4*)(g_h2 + (size_t)p2.x * DOUT))[l];
        float4 v3 = ((const float4*)(g_h2 + (size_t)p3.x * DOUT))[l];
        acc.x = fmaf(v0.x, w0, fmaf(v1.x, w1, fmaf(v2.x, w2, fmaf(v3.x, w3, acc.x))));
        acc.y = fmaf(v0.y, w0, fmaf(v1.y, w1, fmaf(v2.y, w2, fmaf(v3.y, w3, acc.y))));
        acc.z = fmaf(v0.z, w0, fmaf(v1.z, w1, fmaf(v2.z, w2, fmaf(v3.z, w3, acc.z))));
        acc.w = fmaf(v0.w, w0, fmaf(v1.w, w1, fmaf(v2.w, w2, fmaf(v3.w, w3, acc.w))));
    }
    for (; e < end; e++) {
        int2 p = g_epack[e];
        float w = __int_as_float(p.y);
        float4 v = ((const float4*)(g_h2 + (size_t)p.x * DOUT))[l];
        acc.x = fmaf(v.x, w, acc.x);
        acc.y = fmaf(v.y, w, acc.y);
        acc.z = fmaf(v.z, w, acc.z);
        acc.w = fmaf(v.w, w, acc.w);
    }
    float4 b = ((const float4*)b2)[l];
    acc.x += b.x; acc.y += b.y; acc.z += b.z; acc.w += b.w;
    ((float4*)(out + (size_t)node * DOUT))[l] = acc;
}

// ---------------- launch ----------------
extern "C" void kernel_launch(void* const* d_in, const int* in_sizes, int n_in,
                              void* d_out, int out_size) {
    const float* x  = (const float*)d_in[0];
    const void*  ei = d_in[1];                 // int32 or int64 — detected on device
    const float* W1 = (const float*)d_in[2];
    const float* b1 = (const float*)d_in[3];
    const float* W2 = (const float*)d_in[4];
    const float* b2 = (const float*)d_in[5];
    float*       out = (float*)d_out;

    float *h1, *agg1, *h2;
    cudaGetSymbolAddress((void**)&h1, g_h1);
    cudaGetSymbolAddress((void**)&agg1, g_agg1);
    cudaGetSymbolAddress((void**)&h2, g_h2);

    const int T = 256;

    // init (zero + dtype detect) + CSR build + normalization
    k_init<<<(N_NODES + T - 1) / T, T>>>((const int*)ei);
    k_count<<<(N_EDGES + T - 1) / T, T>>>(ei);
    k_scan_a<<<SCAN_NB, SCAN_B>>>();
    k_scan_b<<<1, SCAN_B>>>();
    k_scan_c<<<SCAN_NB, SCAN_B>>>();
    k_fill<<<(N_EDGES + T - 1) / T, T>>>(ei);

    // layer 1: h1 = x @ W1 ; agg1 = normalized aggregation (incl. self loop)
    k_gemm<DH, false><<<(N_NODES + 127) / 128, T>>>(x, W1, nullptr, h1);
    k_gather1<<<(N_NODES * 32 + T - 1) / T, T>>>();

    // layer 2: h2 = relu(agg1 + b1) @ W2 ; out = aggregation + b2
    k_gemm<DOUT, true><<<(N_NODES + 127) / 128, T>>>(agg1, W2, b1, h2);
    k_gather2<<<(N_NODES / 2 * 32 + T - 1) / T, T>>>(b2, out);
}

// round 11
// speedup vs baseline: 1.2103x; 1.2103x over previous
#include <cuda_runtime.h>
#include <cuda_bf16.h>
#include <mma.h>
#include <cstdint>

using namespace nvcuda;

#define N_NODES 40000
#define N_EDGES 640000
#define DIN 128
#define DH 128
#define DOUT 64

#define SCAN_B 256
#define SCAN_NB ((N_NODES + SCAN_B - 1) / SCAN_B)   // 157
#define NT ((N_NODES + 127) / 128)                   // 313 M-tiles
#define GEMM_GRID 152

// ---------------- scratch (no allocations allowed) ----------------
__device__ int   g_is64;
__device__ int   g_cnt[N_NODES];
__device__ int   g_rowptr[N_NODES + 1];
__device__ int   g_cursor[N_NODES];
__device__ int   g_bsum[SCAN_B];
__device__ int   g_boff[SCAN_B];
__device__ int2  g_epack[N_EDGES];                   // {src, norm-weight bits}
__device__ float g_dinv[N_NODES];
__device__ float g_h1[(size_t)N_NODES * DH];         // gemm1 out (fp32)
__device__ float g_h2[(size_t)N_NODES * DOUT];       // gemm2 out (fp32)
// bf16 hi/lo split operands (A matrices row-major [row][k], B row-major [k][n])
__device__ __align__(16) __nv_bfloat16 g_xhi[(size_t)N_NODES * DIN];
__device__ __align__(16) __nv_bfloat16 g_xlo[(size_t)N_NODES * DIN];
__device__ __align__(16) __nv_bfloat16 g_a2hi[(size_t)N_NODES * DH];
__device__ __align__(16) __nv_bfloat16 g_a2lo[(size_t)N_NODES * DH];
__device__ __align__(16) __nv_bfloat16 g_b1hi[DIN * DH];
__device__ __align__(16) __nv_bfloat16 g_b1lo[DIN * DH];
__device__ __align__(16) __nv_bfloat16 g_b2hi[DH * DOUT];
__device__ __align__(16) __nv_bfloat16 g_b2lo[DH * DOUT];

// ---------------- init: zero counts + dtype detection ----------------
__global__ void k_init(const int* __restrict__ ei) {
    int i = blockIdx.x * blockDim.x + threadIdx.x;
    if (i < N_NODES) g_cnt[i] = 0;
    if (blockIdx.x == 0) {
        __shared__ int any_nz;
        if (threadIdx.x == 0) any_nz = 0;
        __syncthreads();
        int nz = 0;
        for (int j = threadIdx.x; j < 4096; j += blockDim.x)
            if (ei[2 * j + 1] != 0) nz = 1;
        if (nz) any_nz = 1;
        __syncthreads();
        if (threadIdx.x == 0) g_is64 = any_nz ? 0 : 1;
    }
}

__device__ __forceinline__ int edge_idx(const void* ei, int which, int e, int is64) {
    if (is64) return (int)((const long long*)ei)[(size_t)which * N_EDGES + e];
    return ((const int*)ei)[which * N_EDGES + e];
}

// ---------------- CSR build ----------------
__global__ void k_count(const void* __restrict__ ei) {
    int e = blockIdx.x * blockDim.x + threadIdx.x;
    if (e < N_EDGES) {
        int d = edge_idx(ei, 1, e, g_is64);
        if ((unsigned)d < N_NODES) atomicAdd(&g_cnt[d], 1);
    }
}

__global__ void k_scan_a() {
    __shared__ int sh[SCAN_B];
    int i = blockIdx.x * SCAN_B + threadIdx.x;
    int v = (i < N_NODES) ? g_cnt[i] : 0;
    sh[threadIdx.x] = v;
    __syncthreads();
#pragma unroll
    for (int off = 1; off < SCAN_B; off <<= 1) {
        int t = (threadIdx.x >= off) ? sh[threadIdx.x - off] : 0;
        __syncthreads();
        sh[threadIdx.x] += t;
        __syncthreads();
    }
    if (i < N_NODES) g_rowptr[i] = sh[threadIdx.x] - v;
    if (threadIdx.x == SCAN_B - 1) g_bsum[blockIdx.x] = sh[threadIdx.x];
}

__global__ void k_scan_b() {
    __shared__ int sh[SCAN_B];
    int v = (threadIdx.x < SCAN_NB) ? g_bsum[threadIdx.x] : 0;
    sh[threadIdx.x] = v;
    __syncthreads();
#pragma unroll
    for (int off = 1; off < SCAN_B; off <<= 1) {
        int t = (threadIdx.x >= off) ? sh[threadIdx.x - off] : 0;
        __syncthreads();
        sh[threadIdx.x] += t;
        __syncthreads();
    }
    if (threadIdx.x < SCAN_NB) g_boff[threadIdx.x] = sh[threadIdx.x] - v;
    if (threadIdx.x == SCAN_NB - 1) g_rowptr[N_NODES] = sh[threadIdx.x];
}

__global__ void k_scan_c() {
    int i = blockIdx.x * SCAN_B + threadIdx.x;
    if (i < N_NODES) {
        int r = g_rowptr[i] + g_boff[blockIdx.x];
        g_rowptr[i] = r;
        g_cursor[i] = r;
        g_dinv[i] = rsqrtf((float)(g_cnt[i] + 1));
    }
}

__global__ void k_fill(const void* __restrict__ ei) {
    int e = blockIdx.x * blockDim.x + threadIdx.x;
    if (e < N_EDGES) {
        int is64 = g_is64;
        int d = edge_idx(ei, 1, e, is64);
        int s = edge_idx(ei, 0, e, is64);
        if ((unsigned)d < N_NODES && (unsigned)s < N_NODES) {
            int pos = atomicAdd(&g_cursor[d], 1);
            float w = g_dinv[s] * g_dinv[d];
            g_epack[pos] = make_int2(s, __float_as_int(w));
        }
    }
}

// ---------------- bf16 hi/lo helpers ----------------
__device__ __forceinline__ void split2(float a, float b, uint32_t& hi, uint32_t& lo) {
    __nv_bfloat16 ha = __float2bfloat16(a), hb = __float2bfloat16(b);
    float ra = a - __bfloat162float(ha), rb = b - __bfloat162float(hb);
    __nv_bfloat16 la = __float2bfloat16(ra), lb = __float2bfloat16(rb);
    hi = (uint32_t)__bfloat16_as_ushort(ha) | ((uint32_t)__bfloat16_as_ushort(hb) << 16);
    lo = (uint32_t)__bfloat16_as_ushort(la) | ((uint32_t)__bfloat16_as_ushort(lb) << 16);
}

// x (fp32) -> hi/lo bf16, row-major
__global__ void k_cvtx(const float* __restrict__ x) {
    int idx = blockIdx.x * blockDim.x + threadIdx.x;          // float4 index
    if (idx < N_NODES * DIN / 4) {
        float4 v = ((const float4*)x)[idx];
        uint2 h, l;
        split2(v.x, v.y, h.x, l.x);
        split2(v.z, v.w, h.y, l.y);
        ((uint2*)g_xhi)[idx] = h;
        ((uint2*)g_xlo)[idx] = l;
    }
}

// W1 [128][128], W2 [128][64] fp32 -> bf16 hi/lo, same row-major layout
__global__ void k_prep_w(const float* __restrict__ W1, const float* __restrict__ W2) {
    int i = blockIdx.x * blockDim.x + threadIdx.x;
    if (i < DIN * DH) {
        float v = W1[i];
        __nv_bfloat16 h = __float2bfloat16(v);
        g_b1hi[i] = h;
        g_b1lo[i] = __float2bfloat16(v - __bfloat162float(h));
    }
    int j = i - DIN * DH;
    if (j >= 0 && j < DH * DOUT) {
        float v = W2[j];
        __nv_bfloat16 h = __float2bfloat16(v);
        g_b2hi[j] = h;
        g_b2lo[j] = __float2bfloat16(v - __bfloat162float(h));
    }
}

// ---------------- WMMA bf16 GEMM: C[40000,N] = A[40000,128] @ B[128,N] ----------------
// hi/lo split, fp32 accum: acc += Ah*Bh + Ah*Bl + Al*Bh. Persistent blocks; B SMEM-resident.
template <int N>
__global__ void __launch_bounds__(256, 1) k_gemm_wmma(
    const __nv_bfloat16* __restrict__ Ahi, const __nv_bfloat16* __restrict__ Alo,
    const __nv_bfloat16* __restrict__ Bhi, const __nv_bfloat16* __restrict__ Blo,
    float* __restrict__ C) {
    constexpr int K = 128, BM = 128;
    constexpr int LDA = K + 8;        // padded to dodge LDSM bank conflicts
    constexpr int LDB = N + 8;
    extern __shared__ __nv_bfloat16 sm[];
    __nv_bfloat16* sAh = sm;                         // [BM][LDA]
    __nv_bfloat16* sAl = sAh + BM * LDA;
    __nv_bfloat16* sBh = sAl + BM * LDA;             // [K][LDB]
    __nv_bfloat16* sBl = sBh + K * LDB;

    const int tid = threadIdx.x, wid = tid >> 5;

    // stage B (hi/lo) once per block
    constexpr int NQ = N / 8;                        // uint4 per row
    for (int idx = tid; idx < K * NQ; idx += 256) {
        int r = idx / NQ, cq = idx % NQ;
        *(uint4*)(sBh + r * LDB + cq * 8) = ((const uint4*)(Bhi + (size_t)r * N))[cq];
        *(uint4*)(sBl + r * LDB + cq * 8) = ((const uint4*)(Blo + (size_t)r * N))[cq];
    }

    // warp tiling: 4 (m) x 2 (n); warp tile 32 x WN
    constexpr int WN = (N == 128) ? 64 : 32;
    constexpr int NFRAG = WN / 16;                   // 4 or 2
    const int wm = (wid >> 1) * 32;
    const int wn = (wid & 1) * WN;

    for (int t = blockIdx.x; t < NT; t += gridDim.x) {
        int row0 = t * BM;
        // stage A tile hi/lo: 128 rows x 128 cols; 16 rows per pass, 8 passes
#pragma unroll
        for (int p = 0; p < 8; p++) {
            int r = p * 16 + (tid >> 4);
            int cq = tid & 15;
            int grow = row0 + r;
            uint4 vh = make_uint4(0, 0, 0, 0), vl = make_uint4(0, 0, 0, 0);
            if (grow < N_NODES) {
                vh = ((const uint4*)(Ahi + (size_t)grow * K))[cq];
                vl = ((const uint4*)(Alo + (size_t)grow * K))[cq];
            }
            *(uint4*)(sAh + r * LDA + cq * 8) = vh;
            *(uint4*)(sAl + r * LDA + cq * 8) = vl;
        }
        __syncthreads();

        wmma::fragment<wmma::accumulator, 16, 16, 16, float> acc[2][NFRAG];
#pragma unroll
        for (int i = 0; i < 2; i++)
#pragma unroll
            for (int j = 0; j < NFRAG; j++) wmma::fill_fragment(acc[i][j], 0.0f);

#pragma unroll
        for (int k = 0; k < K; k += 16) {
            wmma::fragment<wmma::matrix_a, 16, 16, 16, __nv_bfloat16, wmma::row_major> ah[2], al[2];
#pragma unroll
            for (int i = 0; i < 2; i++) {
                wmma::load_matrix_sync(ah[i], sAh + (wm + i * 16) * LDA + k, LDA);
                wmma::load_matrix_sync(al[i], sAl + (wm + i * 16) * LDA + k, LDA);
            }
#pragma unroll
            for (int j = 0; j < NFRAG; j++) {
                wmma::fragment<wmma::matrix_b, 16, 16, 16, __nv_bfloat16, wmma::row_major> bh, bl;
                wmma::load_matrix_sync(bh, sBh + k * LDB + wn + j * 16, LDB);
                wmma::load_matrix_sync(bl, sBl + k * LDB + wn + j * 16, LDB);
#pragma unroll
                for (int i = 0; i < 2; i++) {
                    wmma::mma_sync(acc[i][j], ah[i], bh, acc[i][j]);
                    wmma::mma_sync(acc[i][j], ah[i], bl, acc[i][j]);
                    wmma::mma_sync(acc[i][j], al[i], bh, acc[i][j]);
                }
            }
        }

        // store: 40000 % 16 == 0, so 16-row fragments are all-in or all-out
#pragma unroll
        for (int i = 0; i < 2; i++) {
            int grow = row0 + wm + i * 16;
            if (grow < N_NODES) {
#pragma unroll
                for (int j = 0; j < NFRAG; j++)
                    wmma::store_matrix_sync(C + (size_t)grow * N + wn + j * 16, acc[i][j],
                                            N, wmma::mem_row_major);
            }
        }
        __syncthreads();
    }
}

// ---------------- gather layer 1: one warp per node; emits relu(agg+b1) as bf16 hi/lo ----------------
__global__ void k_gather1(const float* __restrict__ b1) {
    int node = (blockIdx.x * blockDim.x + threadIdx.x) >> 5;
    if (node >= N_NODES) return;
    int lane = threadIdx.x & 31;

    float dd = g_dinv[node];
    float self = dd * dd;
    float4 acc = ((const float4*)(g_h1 + (size_t)node * DH))[lane];
    acc.x *= self; acc.y *= self; acc.z *= self; acc.w *= self;

    int e = g_rowptr[node];
    int end = g_rowptr[node + 1];
    for (; e + 3 < end; e += 4) {
        int2 p0 = g_epack[e],     p1 = g_epack[e + 1];
        int2 p2 = g_epack[e + 2], p3 = g_epack[e + 3];
        float w0 = __int_as_float(p0.y), w1 = __int_as_float(p1.y);
        float w2 = __int_as_float(p2.y), w3 = __int_as_float(p3.y);
        float4 v0 = ((const float4*)(g_h1 + (size_t)p0.x * DH))[lane];
        float4 v1 = ((const float4*)(g_h1 + (size_t)p1.x * DH))[lane];
        float4 v2 = ((const float4*)(g_h1 + (size_t)p2.x * DH))[lane];
        float4 v3 = ((const float4*)(g_h1 + (size_t)p3.x * DH))[lane];
        acc.x = fmaf(v0.x, w0, fmaf(v1.x, w1, fmaf(v2.x, w2, fmaf(v3.x, w3, acc.x))));
        acc.y = fmaf(v0.y, w0, fmaf(v1.y, w1, fmaf(v2.y, w2, fmaf(v3.y, w3, acc.y))));
        acc.z = fmaf(v0.z, w0, fmaf(v1.z, w1, fmaf(v2.z, w2, fmaf(v3.z, w3, acc.z))));
        acc.w = fmaf(v0.w, w0, fmaf(v1.w, w1, fmaf(v2.w, w2, fmaf(v3.w, w3, acc.w))));
    }
    for (; e < end; e++) {
        int2 p = g_epack[e];
        float w = __int_as_float(p.y);
        float4 v = ((const float4*)(g_h1 + (size_t)p.x * DH))[lane];
        acc.x = fmaf(v.x, w, acc.x);
        acc.y = fmaf(v.y, w, acc.y);
        acc.z = fmaf(v.z, w, acc.z);
        acc.w = fmaf(v.w, w, acc.w);
    }
    float4 bb = ((const float4*)b1)[lane];
    float t0 = fmaxf(acc.x + bb.x, 0.0f), t1 = fmaxf(acc.y + bb.y, 0.0f);
    float t2 = fmaxf(acc.z + bb.z, 0.0f), t3 = fmaxf(acc.w + bb.w, 0.0f);
    uint2 h, l;
    split2(t0, t1, h.x, l.x);
    split2(t2, t3, h.y, l.y);
    ((uint2*)(g_a2hi + (size_t)node * DH))[lane] = h;
    ((uint2*)(g_a2lo + (size_t)node * DH))[lane] = l;
}

// ---------------- gather layer 2 (C=64): half-warp per node, + b2 ----------------
__global__ void k_gather2(const float* __restrict__ b2, float* __restrict__ out) {
    int gw = (blockIdx.x * blockDim.x + threadIdx.x) >> 5;
    int lane = threadIdx.x & 31;
    int node = gw * 2 + (lane >> 4);
    if (node >= N_NODES) return;
    int l = lane & 15;

    float dd = g_dinv[node];
    float self = dd * dd;
    float4 acc = ((const float4*)(g_h2 + (size_t)node * DOUT))[l];
    acc.x *= self; acc.y *= self; acc.z *= self; acc.w *= self;

    int e = g_rowptr[node];
    int end = g_rowptr[node + 1];
    for (; e + 3 < end; e += 4) {
        int2 p0 = g_epack[e],     p1 = g_epack[e + 1];
        int2 p2 = g_epack[e + 2], p3 = g_epack[e + 3];
        float w0 = __int_as_float(p0.y), w1 = __int_as_float(p1.y);
        float w2 = __int_as_float(p2.y), w3 = __int_as_float(p3.y);
        float4 v0 = ((const float4*)(g_h2 + (size_t)p0.x * DOUT))[l];
        float4 v1 = ((const float4*)(g_h2 + (size_t)p1.x * DOUT))[l];
        float4 v2 = ((const float4*)(g_h2 + (size_t)p2.x * DOUT))[l];
        float4 v3 = ((const float4*)(g_h2 + (size_t)p3.x * DOUT))[l];
        acc.x = fmaf(v0.x, w0, fmaf(v1.x, w1, fmaf(v2.x, w2, fmaf(v3.x, w3, acc.x))));
        acc.y = fmaf(v0.y, w0, fmaf(v1.y, w1, fmaf(v2.y, w2, fmaf(v3.y, w3, acc.y))));
        acc.z = fmaf(v0.z, w0, fmaf(v1.z, w1, fmaf(v2.z, w2, fmaf(v3.z, w3, acc.z))));
        acc.w = fmaf(v0.w, w0, fmaf(v1.w, w1, fmaf(v2.w, w2, fmaf(v3.w, w3, acc.w))));
    }
    for (; e < end; e++) {
        int2 p = g_epack[e];
        float w = __int_as_float(p.y);
        float4 v = ((const float4*)(g_h2 + (size_t)p.x * DOUT))[l];
        acc.x = fmaf(v.x, w, acc.x);
        acc.y = fmaf(v.y, w, acc.y);
        acc.z = fmaf(v.z, w, acc.z);
        acc.w = fmaf(v.w, w, acc.w);
    }
    float4 b = ((const float4*)b2)[l];
    acc.x += b.x; acc.y += b.y; acc.z += b.z; acc.w += b.w;
    ((float4*)(out + (size_t)node * DOUT))[l] = acc;
}

// ---------------- launch ----------------
extern "C" void kernel_launch(void* const* d_in, const int* in_sizes, int n_in,
                              void* d_out, int out_size) {
    const float* x  = (const float*)d_in[0];
    const void*  ei = d_in[1];
    const float* W1 = (const float*)d_in[2];
    const float* b1 = (const float*)d_in[3];
    const float* W2 = (const float*)d_in[4];
    const float* b2 = (const float*)d_in[5];
    float*       out = (float*)d_out;

    float *h1, *h2;
    __nv_bfloat16 *xhi, *xlo, *a2hi, *a2lo, *b1hi, *b1lo, *b2hi, *b2lo;
    cudaGetSymbolAddress((void**)&h1, g_h1);
    cudaGetSymbolAddress((void**)&h2, g_h2);
    cudaGetSymbolAddress((void**)&xhi, g_xhi);
    cudaGetSymbolAddress((void**)&xlo, g_xlo);
    cudaGetSymbolAddress((void**)&a2hi, g_a2hi);
    cudaGetSymbolAddress((void**)&a2lo, g_a2lo);
    cudaGetSymbolAddress((void**)&b1hi, g_b1hi);
    cudaGetSymbolAddress((void**)&b1lo, g_b1lo);
    cudaGetSymbolAddress((void**)&b2hi, g_b2hi);
    cudaGetSymbolAddress((void**)&b2lo, g_b2lo);

    // smem: A hi/lo [128][136] + B hi/lo [128][N+8], bf16
    const int SM1 = (2 * 128 * 136 + 2 * 128 * (DH + 8)) * 2;     // 139264 B
    const int SM2 = (2 * 128 * 136 + 2 * 128 * (DOUT + 8)) * 2;   // 106496 B
    cudaFuncSetAttribute(k_gemm_wmma<DH>,   cudaFuncAttributeMaxDynamicSharedMemorySize, SM1);
    cudaFuncSetAttribute(k_gemm_wmma<DOUT>, cudaFuncAttributeMaxDynamicSharedMemorySize, SM2);

    const int T = 256;

    // prep: dtype detect + bf16 splits + CSR build
    k_init<<<(N_NODES + T - 1) / T, T>>>((const int*)ei);
    k_cvtx<<<(N_NODES * DIN / 4 + T - 1) / T, T>>>(x);
    k_prep_w<<<(DIN * DH + DH * DOUT + T - 1) / T, T>>>(W1, W2);
    k_count<<<(N_EDGES + T - 1) / T, T>>>(ei);
    k_scan_a<<<SCAN_NB, SCAN_B>>>();
    k_scan_b<<<1, SCAN_B>>>();
    k_scan_c<<<SCAN_NB, SCAN_B>>>();
    k_fill<<<(N_EDGES + T - 1) / T, T>>>(ei);

    // layer 1
    k_gemm_wmma<DH><<<GEMM_GRID, T, SM1>>>(xhi, xlo, b1hi, b1lo, h1);
    k_gather1<<<(N_NODES * 32 + T - 1) / T, T>>>(b1);

    // layer 2
    k_gemm_wmma<DOUT><<<GEMM_GRID, T, SM2>>>(a2hi, a2lo, b2hi, b2lo, h2);
    k_gather2<<<(N_NODES / 2 * 32 + T - 1) / T, T>>>(b2, out);
}

// round 12
// speedup vs baseline: 1.2319x; 1.0178x over previous
#include <cuda_runtime.h>
#include <cuda_bf16.h>
#include <mma.h>
#include <cstdint>

using namespace nvcuda;

#define N_NODES 40000
#define N_EDGES 640000
#define DIN 128
#define DH 128
#define DOUT 64

#define SCAN_B 256
#define SCAN_NB ((N_NODES + SCAN_B - 1) / SCAN_B)   // 157
#define NT ((N_NODES + 127) / 128)                   // 313 M-tiles
#define GEMM_GRID 152

// ---------------- scratch (no allocations allowed) ----------------
__device__ int   g_is64;
__device__ int   g_cnt[N_NODES];
__device__ int   g_rowptr[N_NODES + 1];
__device__ int   g_cursor[N_NODES];
__device__ int   g_bsum[SCAN_B];
__device__ int   g_boff[SCAN_B];
__device__ int2  g_epack[N_EDGES];                   // {src, norm-weight bits}
__device__ float g_dinv[N_NODES];
__device__ float g_h1[(size_t)N_NODES * DH];         // gemm1 out (fp32)
__device__ float g_agg1[(size_t)N_NODES * DH];       // relu(agg + b1) fp32
__device__ float g_h2[(size_t)N_NODES * DOUT];       // gemm2 out (fp32)
// weights bf16 hi/lo, row-major [k][n]
__device__ __align__(16) __nv_bfloat16 g_b1hi[DIN * DH];
__device__ __align__(16) __nv_bfloat16 g_b1lo[DIN * DH];
__device__ __align__(16) __nv_bfloat16 g_b2hi[DH * DOUT];
__device__ __align__(16) __nv_bfloat16 g_b2lo[DH * DOUT];

// ---------------- init: zero counts + dtype detection ----------------
__global__ void k_init(const int* __restrict__ ei) {
    int i = blockIdx.x * blockDim.x + threadIdx.x;
    if (i < N_NODES) g_cnt[i] = 0;
    if (blockIdx.x == 0) {
        __shared__ int any_nz;
        if (threadIdx.x == 0) any_nz = 0;
        __syncthreads();
        int nz = 0;
        for (int j = threadIdx.x; j < 4096; j += blockDim.x)
            if (ei[2 * j + 1] != 0) nz = 1;
        if (nz) any_nz = 1;
        __syncthreads();
        if (threadIdx.x == 0) g_is64 = any_nz ? 0 : 1;
    }
}

__device__ __forceinline__ int edge_idx(const void* ei, int which, int e, int is64) {
    if (is64) return (int)((const long long*)ei)[(size_t)which * N_EDGES + e];
    return ((const int*)ei)[which * N_EDGES + e];
}

// ---------------- CSR build ----------------
__global__ void k_count(const void* __restrict__ ei) {
    int e = blockIdx.x * blockDim.x + threadIdx.x;
    if (e < N_EDGES) {
        int d = edge_idx(ei, 1, e, g_is64);
        if ((unsigned)d < N_NODES) atomicAdd(&g_cnt[d], 1);
    }
}

__global__ void k_scan_a() {
    __shared__ int sh[SCAN_B];
    int i = blockIdx.x * SCAN_B + threadIdx.x;
    int v = (i < N_NODES) ? g_cnt[i] : 0;
    sh[threadIdx.x] = v;
    __syncthreads();
#pragma unroll
    for (int off = 1; off < SCAN_B; off <<= 1) {
        int t = (threadIdx.x >= off) ? sh[threadIdx.x - off] : 0;
        __syncthreads();
        sh[threadIdx.x] += t;
        __syncthreads();
    }
    if (i < N_NODES) g_rowptr[i] = sh[threadIdx.x] - v;
    if (threadIdx.x == SCAN_B - 1) g_bsum[blockIdx.x] = sh[threadIdx.x];
}

__global__ void k_scan_b() {
    __shared__ int sh[SCAN_B];
    int v = (threadIdx.x < SCAN_NB) ? g_bsum[threadIdx.x] : 0;
    sh[threadIdx.x] = v;
    __syncthreads();
#pragma unroll
    for (int off = 1; off < SCAN_B; off <<= 1) {
        int t = (threadIdx.x >= off) ? sh[threadIdx.x - off] : 0;
        __syncthreads();
        sh[threadIdx.x] += t;
        __syncthreads();
    }
    if (threadIdx.x < SCAN_NB) g_boff[threadIdx.x] = sh[threadIdx.x] - v;
    if (threadIdx.x == SCAN_NB - 1) g_rowptr[N_NODES] = sh[threadIdx.x];
}

__global__ void k_scan_c() {
    int i = blockIdx.x * SCAN_B + threadIdx.x;
    if (i < N_NODES) {
        int r = g_rowptr[i] + g_boff[blockIdx.x];
        g_rowptr[i] = r;
        g_cursor[i] = r;
        g_dinv[i] = rsqrtf((float)(g_cnt[i] + 1));
    }
}

__global__ void k_fill(const void* __restrict__ ei) {
    int e = blockIdx.x * blockDim.x + threadIdx.x;
    if (e < N_EDGES) {
        int is64 = g_is64;
        int d = edge_idx(ei, 1, e, is64);
        int s = edge_idx(ei, 0, e, is64);
        if ((unsigned)d < N_NODES && (unsigned)s < N_NODES) {
            int pos = atomicAdd(&g_cursor[d], 1);
            float w = g_dinv[s] * g_dinv[d];
            g_epack[pos] = make_int2(s, __float_as_int(w));
        }
    }
}

// ---------------- bf16 hi/lo helpers ----------------
__device__ __forceinline__ void split2(float a, float b, uint32_t& hi, uint32_t& lo) {
    __nv_bfloat16 ha = __float2bfloat16(a), hb = __float2bfloat16(b);
    float ra = a - __bfloat162float(ha), rb = b - __bfloat162float(hb);
    __nv_bfloat16 la = __float2bfloat16(ra), lb = __float2bfloat16(rb);
    hi = (uint32_t)__bfloat16_as_ushort(ha) | ((uint32_t)__bfloat16_as_ushort(hb) << 16);
    lo = (uint32_t)__bfloat16_as_ushort(la) | ((uint32_t)__bfloat16_as_ushort(lb) << 16);
}

// W1 [128][128], W2 [128][64] fp32 -> bf16 hi/lo, same row-major layout
__global__ void k_prep_w(const float* __restrict__ W1, const float* __restrict__ W2) {
    int i = blockIdx.x * blockDim.x + threadIdx.x;
    if (i < DIN * DH) {
        float v = W1[i];
        __nv_bfloat16 h = __float2bfloat16(v);
        g_b1hi[i] = h;
        g_b1lo[i] = __float2bfloat16(v - __bfloat162float(h));
    }
    int j = i - DIN * DH;
    if (j >= 0 && j < DH * DOUT) {
        float v = W2[j];
        __nv_bfloat16 h = __float2bfloat16(v);
        g_b2hi[j] = h;
        g_b2lo[j] = __float2bfloat16(v - __bfloat162float(h));
    }
}

// ---------------- WMMA bf16 GEMM: C[40000,N] = A[40000,128] @ B[128,N] ----------------
// A is fp32 in GMEM; split to bf16 hi/lo in registers during SMEM staging.
// hi/lo, fp32 accum: acc += Ah*Bh + Ah*Bl + Al*Bh. Persistent blocks; B SMEM-resident.
template <int N>
__global__ void __launch_bounds__(256, 1) k_gemm_wmma(
    const float* __restrict__ A,
    const __nv_bfloat16* __restrict__ Bhi, const __nv_bfloat16* __restrict__ Blo,
    float* __restrict__ C) {
    constexpr int K = 128, BM = 128;
    constexpr int LDA = K + 8;        // padded to dodge LDSM bank conflicts
    constexpr int LDB = N + 8;
    extern __shared__ __nv_bfloat16 sm[];
    __nv_bfloat16* sAh = sm;                         // [BM][LDA]
    __nv_bfloat16* sAl = sAh + BM * LDA;
    __nv_bfloat16* sBh = sAl + BM * LDA;             // [K][LDB]
    __nv_bfloat16* sBl = sBh + K * LDB;

    const int tid = threadIdx.x, wid = tid >> 5;

    // stage B (hi/lo) once per block
    constexpr int NQ = N / 8;                        // uint4 per row
    for (int idx = tid; idx < K * NQ; idx += 256) {
        int r = idx / NQ, cq = idx % NQ;
        *(uint4*)(sBh + r * LDB + cq * 8) = ((const uint4*)(Bhi + (size_t)r * N))[cq];
        *(uint4*)(sBl + r * LDB + cq * 8) = ((const uint4*)(Blo + (size_t)r * N))[cq];
    }

    // warp tiling: 4 (m) x 2 (n); warp tile 32 x WN
    constexpr int WN = (N == 128) ? 64 : 32;
    constexpr int NFRAG = WN / 16;                   // 4 or 2
    const int wm = (wid >> 1) * 32;
    const int wn = (wid & 1) * WN;

    for (int t = blockIdx.x; t < NT; t += gridDim.x) {
        int row0 = t * BM;
        // stage A tile: 128 rows x 128 fp32 cols = 4096 float4; 16 per thread.
        // idx -> row = idx>>5, float4-col cq = idx&31. Split to hi/lo on the fly.
#pragma unroll
        for (int p = 0; p < 16; p++) {
            int idx = p * 256 + tid;
            int r = idx >> 5;
            int cq = idx & 31;
            int grow = row0 + r;
            float4 v = make_float4(0.f, 0.f, 0.f, 0.f);
            if (grow < N_NODES) v = ((const float4*)(A + (size_t)grow * K))[cq];
            uint2 h, l;
            split2(v.x, v.y, h.x, l.x);
            split2(v.z, v.w, h.y, l.y);
            *(uint2*)(sAh + r * LDA + cq * 4) = h;
            *(uint2*)(sAl + r * LDA + cq * 4) = l;
        }
        __syncthreads();

        wmma::fragment<wmma::accumulator, 16, 16, 16, float> acc[2][NFRAG];
#pragma unroll
        for (int i = 0; i < 2; i++)
#pragma unroll
            for (int j = 0; j < NFRAG; j++) wmma::fill_fragment(acc[i][j], 0.0f);

#pragma unroll
        for (int k = 0; k < K; k += 16) {
            wmma::fragment<wmma::matrix_a, 16, 16, 16, __nv_bfloat16, wmma::row_major> ah[2], al[2];
#pragma unroll
            for (int i = 0; i < 2; i++) {
                wmma::load_matrix_sync(ah[i], sAh + (wm + i * 16) * LDA + k, LDA);
                wmma::load_matrix_sync(al[i], sAl + (wm + i * 16) * LDA + k, LDA);
            }
#pragma unroll
            for (int j = 0; j < NFRAG; j++) {
                wmma::fragment<wmma::matrix_b, 16, 16, 16, __nv_bfloat16, wmma::row_major> bh, bl;
                wmma::load_matrix_sync(bh, sBh + k * LDB + wn + j * 16, LDB);
                wmma::load_matrix_sync(bl, sBl + k * LDB + wn + j * 16, LDB);
#pragma unroll
                for (int i = 0; i < 2; i++) {
                    wmma::mma_sync(acc[i][j], ah[i], bh, acc[i][j]);
                    wmma::mma_sync(acc[i][j], ah[i], bl, acc[i][j]);
                    wmma::mma_sync(acc[i][j], al[i], bh, acc[i][j]);
                }
            }
        }

        // store: 40000 % 16 == 0, so 16-row fragments are all-in or all-out
#pragma unroll
        for (int i = 0; i < 2; i++) {
            int grow = row0 + wm + i * 16;
            if (grow < N_NODES) {
#pragma unroll
                for (int j = 0; j < NFRAG; j++)
                    wmma::store_matrix_sync(C + (size_t)grow * N + wn + j * 16, acc[i][j],
                                            N, wmma::mem_row_major);
            }
        }
        __syncthreads();
    }
}

// ---------------- gather layer 1: one warp per node; emits relu(agg+b1) fp32 ----------------
__global__ void k_gather1(const float* __restrict__ b1) {
    int node = (blockIdx.x * blockDim.x + threadIdx.x) >> 5;
    if (node >= N_NODES) return;
    int lane = threadIdx.x & 31;

    float dd = g_dinv[node];
    float self = dd * dd;
    float4 acc = ((const float4*)(g_h1 + (size_t)node * DH))[lane];
    acc.x *= self; acc.y *= self; acc.z *= self; acc.w *= self;

    int e = g_rowptr[node];
    int end = g_rowptr[node + 1];
    for (; e + 3 < end; e += 4) {
        int2 p0 = g_epack[e],     p1 = g_epack[e + 1];
        int2 p2 = g_epack[e + 2], p3 = g_epack[e + 3];
        float w0 = __int_as_float(p0.y), w1 = __int_as_float(p1.y);
        float w2 = __int_as_float(p2.y), w3 = __int_as_float(p3.y);
        float4 v0 = ((const float4*)(g_h1 + (size_t)p0.x * DH))[lane];
        float4 v1 = ((const float4*)(g_h1 + (size_t)p1.x * DH))[lane];
        float4 v2 = ((const float4*)(g_h1 + (size_t)p2.x * DH))[lane];
        float4 v3 = ((const float4*)(g_h1 + (size_t)p3.x * DH))[lane];
        acc.x = fmaf(v0.x, w0, fmaf(v1.x, w1, fmaf(v2.x, w2, fmaf(v3.x, w3, acc.x))));
        acc.y = fmaf(v0.y, w0, fmaf(v1.y, w1, fmaf(v2.y, w2, fmaf(v3.y, w3, acc.y))));
        acc.z = fmaf(v0.z, w0, fmaf(v1.z, w1, fmaf(v2.z, w2, fmaf(v3.z, w3, acc.z))));
        acc.w = fmaf(v0.w, w0, fmaf(v1.w, w1, fmaf(v2.w, w2, fmaf(v3.w, w3, acc.w))));
    }
    for (; e < end; e++) {
        int2 p = g_epack[e];
        float w = __int_as_float(p.y);
        float4 v = ((const float4*)(g_h1 + (size_t)p.x * DH))[lane];
        acc.x = fmaf(v.x, w, acc.x);
        acc.y = fmaf(v.y, w, acc.y);
        acc.z = fmaf(v.z, w, acc.z);
        acc.w = fmaf(v.w, w, acc.w);
    }
    float4 bb = ((const float4*)b1)[lane];
    acc.x = fmaxf(acc.x + bb.x, 0.0f);
    acc.y = fmaxf(acc.y + bb.y, 0.0f);
    acc.z = fmaxf(acc.z + bb.z, 0.0f);
    acc.w = fmaxf(acc.w + bb.w, 0.0f);
    ((float4*)(g_agg1 + (size_t)node * DH))[lane] = acc;
}

// ---------------- gather layer 2 (C=64): half-warp per node, + b2 ----------------
__global__ void k_gather2(const float* __restrict__ b2, float* __restrict__ out) {
    int gw = (blockIdx.x * blockDim.x + threadIdx.x) >> 5;
    int lane = threadIdx.x & 31;
    int node = gw * 2 + (lane >> 4);
    if (node >= N_NODES) return;
    int l = lane & 15;

    float dd = g_dinv[node];
    float self = dd * dd;
    float4 acc = ((const float4*)(g_h2 + (size_t)node * DOUT))[l];
    acc.x *= self; acc.y *= self; acc.z *= self; acc.w *= self;

    int e = g_rowptr[node];
    int end = g_rowptr[node + 1];
    for (; e + 3 < end; e += 4) {
        int2 p0 = g_epack[e],     p1 = g_epack[e + 1];
        int2 p2 = g_epack[e + 2], p3 = g_epack[e + 3];
        float w0 = __int_as_float(p0.y), w1 = __int_as_float(p1.y);
        float w2 = __int_as_float(p2.y), w3 = __int_as_float(p3.y);
        float4 v0 = ((const float4*)(g_h2 + (size_t)p0.x * DOUT))[l];
        float4 v1 = ((const float4*)(g_h2 + (size_t)p1.x * DOUT))[l];
        float4 v2 = ((const float4*)(g_h2 + (size_t)p2.x * DOUT))[l];
        float4 v3 = ((const float4*)(g_h2 + (size_t)p3.x * DOUT))[l];
        acc.x = fmaf(v0.x, w0, fmaf(v1.x, w1, fmaf(v2.x, w2, fmaf(v3.x, w3, acc.x))));
        acc.y = fmaf(v0.y, w0, fmaf(v1.y, w1, fmaf(v2.y, w2, fmaf(v3.y, w3, acc.y))));
        acc.z = fmaf(v0.z, w0, fmaf(v1.z, w1, fmaf(v2.z, w2, fmaf(v3.z, w3, acc.z))));
        acc.w = fmaf(v0.w, w0, fmaf(v1.w, w1, fmaf(v2.w, w2, fmaf(v3.w, w3, acc.w))));
    }
    for (; e < end; e++) {
        int2 p = g_epack[e];
        float w = __int_as_float(p.y);
        float4 v = ((const float4*)(g_h2 + (size_t)p.x * DOUT))[l];
        acc.x = fmaf(v.x, w, acc.x);
        acc.y = fmaf(v.y, w, acc.y);
        acc.z = fmaf(v.z, w, acc.z);
        acc.w = fmaf(v.w, w, acc.w);
    }
    float4 b = ((const float4*)b2)[l];
    acc.x += b.x; acc.y += b.y; acc.z += b.z; acc.w += b.w;
    ((float4*)(out + (size_t)node * DOUT))[l] = acc;
}

// ---------------- launch ----------------
extern "C" void kernel_launch(void* const* d_in, const int* in_sizes, int n_in,
                              void* d_out, int out_size) {
    const float* x  = (const float*)d_in[0];
    const void*  ei = d_in[1];
    const float* W1 = (const float*)d_in[2];
    const float* b1 = (const float*)d_in[3];
    const float* W2 = (const float*)d_in[4];
    const float* b2 = (const float*)d_in[5];
    float*       out = (float*)d_out;

    float *h1, *h2, *agg1;
    __nv_bfloat16 *b1hi, *b1lo, *b2hi, *b2lo;
    cudaGetSymbolAddress((void**)&h1, g_h1);
    cudaGetSymbolAddress((void**)&h2, g_h2);
    cudaGetSymbolAddress((void**)&agg1, g_agg1);
    cudaGetSymbolAddress((void**)&b1hi, g_b1hi);
    cudaGetSymbolAddress((void**)&b1lo, g_b1lo);
    cudaGetSymbolAddress((void**)&b2hi, g_b2hi);
    cudaGetSymbolAddress((void**)&b2lo, g_b2lo);

    // smem: A hi/lo [128][136] + B hi/lo [128][N+8], bf16
    const int SM1 = (2 * 128 * 136 + 2 * 128 * (DH + 8)) * 2;     // 139264 B
    const int SM2 = (2 * 128 * 136 + 2 * 128 * (DOUT + 8)) * 2;   // 106496 B
    cudaFuncSetAttribute(k_gemm_wmma<DH>,   cudaFuncAttributeMaxDynamicSharedMemorySize, SM1);
    cudaFuncSetAttribute(k_gemm_wmma<DOUT>, cudaFuncAttributeMaxDynamicSharedMemorySize, SM2);

    const int T = 256;

    // prep: dtype detect + W bf16 split + CSR build
    k_init<<<(N_NODES + T - 1) / T, T>>>((const int*)ei);
    k_prep_w<<<(DIN * DH + DH * DOUT + T - 1) / T, T>>>(W1, W2);
    k_count<<<(N_EDGES + T - 1) / T, T>>>(ei);
    k_scan_a<<<SCAN_NB, SCAN_B>>>();
    k_scan_b<<<1, SCAN_B>>>();
    k_scan_c<<<SCAN_NB, SCAN_B>>>();
    k_fill<<<(N_EDGES + T - 1) / T, T>>>(ei);

    // layer 1
    k_gemm_wmma<DH><<<GEMM_GRID, T, SM1>>>(x, b1hi, b1lo, h1);
    k_gather1<<<(N_NODES * 32 + T - 1) / T, T>>>(b1);

    // layer 2
    k_gemm_wmma<DOUT><<<GEMM_GRID, T, SM2>>>(agg1, b2hi, b2lo, h2);
    k_gather2<<<(N_NODES / 2 * 32 + T - 1) / T, T>>>(b2, out);
}